// round 2
// baseline (speedup 1.0000x reference)
#include <cuda_runtime.h>
#include <cuda_bf16.h>
#include <cstdint>

#define BB 8
#define NN 256
#define MM 16
#define DD 256

// bf16 centroids scratch: [B][N][D]
__device__ __nv_bfloat16 g_C[BB * NN * DD];

// ============================ helpers ============================
__device__ __forceinline__ uint32_t smem_u32(const void* p) {
    uint32_t a;
    asm("{ .reg .u64 t; cvta.to.shared.u64 t, %1; cvt.u32.u64 %0, t; }"
        : "=r"(a) : "l"(p));
    return a;
}

__device__ __forceinline__ float ex2f(float x) {
    float y; asm("ex2.approx.ftz.f32 %0, %1;" : "=f"(y) : "f"(x)); return y;
}
__device__ __forceinline__ float lg2f(float x) {
    float y; asm("lg2.approx.ftz.f32 %0, %1;" : "=f"(y) : "f"(x)); return y;
}

__device__ __forceinline__ void ldm_x4(uint32_t* r, uint32_t addr) {
    asm volatile("ldmatrix.sync.aligned.m8n8.x4.shared.b16 {%0,%1,%2,%3}, [%4];"
                 : "=r"(r[0]), "=r"(r[1]), "=r"(r[2]), "=r"(r[3])
                 : "r"(addr));
}

__device__ __forceinline__ void mma16816(float* d, const uint32_t* a,
                                         uint32_t b0, uint32_t b1) {
    asm volatile(
        "mma.sync.aligned.m16n8k16.row.col.f32.bf16.bf16.f32 "
        "{%0,%1,%2,%3}, {%4,%5,%6,%7}, {%8,%9}, {%0,%1,%2,%3};"
        : "+f"(d[0]), "+f"(d[1]), "+f"(d[2]), "+f"(d[3])
        : "r"(a[0]), "r"(a[1]), "r"(a[2]), "r"(a[3]), "r"(b0), "r"(b1));
}

// ============================ Kernel 1: centroids ============================
__global__ void centroid_kernel(const float* __restrict__ E) {
    int idx = blockIdx.x * blockDim.x + threadIdx.x;  // over B*N*D = 524288
    int d  = idx & (DD - 1);
    int bn = idx >> 8;
    const float* p = E + ((size_t)bn * MM) * DD + d;
    float s = 0.f;
#pragma unroll
    for (int i = 0; i < MM; i++) s += p[i * DD];
    g_C[idx] = __float2bfloat16(s * (1.0f / MM));
}

__global__ void zero_kernel(float* out) { out[0] = 0.0f; }

// ============================ Kernel 2: GEMM + fused LSE ============================
// smem layout (dynamic):
static constexpr int SQN_OFF  = 0;       // 128 floats
static constexpr int MS_OFF   = 512;     // float2[128][2] = 2048 B
static constexpr int SELF_OFF = 2560;    // 128 floats
static constexpr int RED_OFF  = 3072;    // 8 floats
static constexpr int A_OFF    = 4096;    // 128 rows x 512 B = 65536
static constexpr int B_OFF    = 69632;   // 256 rows x 512 B = 131072
static constexpr int SMEM_TOTAL = 200704;

// swizzled byte offset inside a tile: row (512B each), 16B unit index
#define SWZ(row, un) ((uint32_t)(row) * 512u + ((((uint32_t)(un)) ^ ((uint32_t)(row) & 7u)) << 4))

__global__ void __launch_bounds__(256, 1) loss_kernel(
    const float* __restrict__ E,
    const float* __restrict__ wp,
    const float* __restrict__ bp,
    float* __restrict__ out)
{
    extern __shared__ char smem[];
    uint32_t sb = smem_u32(smem);
    int tid = threadIdx.x, wid = tid >> 5, L = tid & 31;
    int warpM = wid & 3, warpN = wid >> 2;   // 4 x 2 warp grid; warp tile 32 x 128

    int batch = blockIdx.x >> 5;   // 8
    int tile  = blockIdx.x & 31;   // 32 j-tiles (128 rows = 8 j-groups x M=16)
    int j0    = tile * 8;

    float w_s = *wp;
    float b_s = *bp;

    float*  sqn  = (float*)(smem + SQN_OFF);
    float2* ms   = (float2*)(smem + MS_OFF);
    float*  SELF = (float*)(smem + SELF_OFF);
    float*  red  = (float*)(smem + RED_OFF);

    // ---- stage B tile: C[batch] bf16 [256 x 256], swizzled ----
    {
        const uint4* Cg = (const uint4*)(g_C + (size_t)batch * NN * DD);
#pragma unroll
        for (int it = 0; it < 32; it++) {
            int u = it * 256 + tid;        // unit index: row*32 + un
            int row = u >> 5, un = u & 31;
            uint4 v = Cg[u];
            *(uint4*)(smem + B_OFF + SWZ(row, un)) = v;
        }
    }

    // ---- stage A tile: E rows fp32 -> bf16, fp32 sq_norm per row ----
    {
        const float4* Eg = (const float4*)E + ((size_t)(batch * 4096 + tile * 128)) * 64;
#pragma unroll
        for (int it = 0; it < 16; it++) {
            int u = it * 256 + tid;        // 16B-unit (8 bf16 = 8 floats source)
            int row = u >> 5, un = u & 31; // row == it*8 + wid  (whole warp same row)
            float4 v0 = Eg[u * 2];
            float4 v1 = Eg[u * 2 + 1];
            float ps = v0.x*v0.x + v0.y*v0.y + v0.z*v0.z + v0.w*v0.w
                     + v1.x*v1.x + v1.y*v1.y + v1.z*v1.z + v1.w*v1.w;
            ps += __shfl_xor_sync(0xFFFFFFFFu, ps, 16);
            ps += __shfl_xor_sync(0xFFFFFFFFu, ps, 8);
            ps += __shfl_xor_sync(0xFFFFFFFFu, ps, 4);
            ps += __shfl_xor_sync(0xFFFFFFFFu, ps, 2);
            ps += __shfl_xor_sync(0xFFFFFFFFu, ps, 1);
            if (L == 0) sqn[row] = ps;     // each (it,wid) -> unique row

            __nv_bfloat162 p0 = __floats2bfloat162_rn(v0.x, v0.y);
            __nv_bfloat162 p1 = __floats2bfloat162_rn(v0.z, v0.w);
            __nv_bfloat162 p2 = __floats2bfloat162_rn(v1.x, v1.y);
            __nv_bfloat162 p3 = __floats2bfloat162_rn(v1.z, v1.w);
            uint4 pk;
            pk.x = *(uint32_t*)&p0; pk.y = *(uint32_t*)&p1;
            pk.z = *(uint32_t*)&p2; pk.w = *(uint32_t*)&p3;
            *(uint4*)(smem + A_OFF + SWZ(row, un)) = pk;
        }
    }
    __syncthreads();

    // ---- per-lane ldmatrix addressing ----
    // A frag f (16x16): lanes 0-7 rows 0-7 @k0 | 8-15 rows 8-15 @k0 | 16-23 rows 0-7 @k8 | 24-31 rows 8-15 @k8
    uint32_t arsk = (uint32_t)((L >> 4) ^ (L & 7));
    uint32_t aB0 = sb + A_OFF + (uint32_t)(warpM * 32 + (L & 15)) * 512u;
    uint32_t aB1 = aB0 + 16 * 512;
    // B frag (n16 x k16): lanes 0-7 n0-7 @k0 | 8-15 n0-7 @k8 | 16-23 n8-15 @k0 | 24-31 n8-15 @k8
    uint32_t brsk = (uint32_t)(((L >> 3) & 1) ^ (L & 7));
    uint32_t bB[8];
#pragma unroll
    for (int nb = 0; nb < 8; nb++)
        bB[nb] = sb + B_OFF +
                 (uint32_t)(warpN * 128 + nb * 16 + ((L >> 4) << 3) + (L & 7)) * 512u;

    float acc[2][16][4];
#pragma unroll
    for (int f = 0; f < 2; f++)
#pragma unroll
        for (int nf = 0; nf < 16; nf++)
#pragma unroll
            for (int q = 0; q < 4; q++) acc[f][nf][q] = 0.f;

    // ---- mainloop: K=256 in 16 steps of k16 ----
#pragma unroll 2
    for (int ks = 0; ks < 16; ks++) {
        uint32_t ku = (uint32_t)(ks * 2);          // 16B-unit index of k-chunk (even)
        uint32_t xa = ((ku ^ arsk) << 4);
        uint32_t xb = ((ku ^ brsk) << 4);
        uint32_t a0[4], a1[4];
        ldm_x4(a0, aB0 + xa);
        ldm_x4(a1, aB1 + xa);
#pragma unroll
        for (int nb = 0; nb < 8; nb++) {
            uint32_t bf[4];
            ldm_x4(bf, bB[nb] + xb);
            mma16816(acc[0][2 * nb],     a0, bf[0], bf[1]);
            mma16816(acc[0][2 * nb + 1], a0, bf[2], bf[3]);
            mma16816(acc[1][2 * nb],     a1, bf[0], bf[1]);
            mma16816(acc[1][2 * nb + 1], a1, bf[2], bf[3]);
        }
    }

    // ---- fused epilogue: per-row logsumexp with leave-one-out diagonal ----
    const float L2E = 1.44269504f, LN2 = 0.69314718f;
    float wdiv = w_s * (1.0f / 15.0f);
#pragma unroll
    for (int f = 0; f < 2; f++) {
        int dk = j0 + warpM * 2 + f;                     // global diag col for these 16 rows
        int cloc = ((dk >> 7) == warpN) ? (dk & 127) : -1;
#pragma unroll
        for (int rh = 0; rh < 2; rh++) {
            int row = warpM * 32 + f * 16 + (L >> 2) + rh * 8;
            float sq = sqn[row];
            float m = -1e30f, sself = 0.f;
#pragma unroll
            for (int nf = 0; nf < 16; nf++) {
#pragma unroll
                for (int cq = 0; cq < 2; cq++) {
                    float v = acc[f][nf][rh * 2 + cq];
                    int col = nf * 8 + (L & 3) * 2 + cq;
                    bool dg = (col == cloc);
                    float xv = dg ? fmaf(wdiv, fmaf(16.f, v, -sq), b_s)
                                  : fmaf(w_s, v, b_s);
                    if (dg) sself = xv;
                    m = fmaxf(m, xv);
                }
            }
            m = fmaxf(m, __shfl_xor_sync(0xFFFFFFFFu, m, 1));
            m = fmaxf(m, __shfl_xor_sync(0xFFFFFFFFu, m, 2));
            float s = 0.f;
#pragma unroll
            for (int nf = 0; nf < 16; nf++) {
#pragma unroll
                for (int cq = 0; cq < 2; cq++) {
                    float v = acc[f][nf][rh * 2 + cq];
                    int col = nf * 8 + (L & 3) * 2 + cq;
                    float xv = (col == cloc) ? fmaf(wdiv, fmaf(16.f, v, -sq), b_s)
                                             : fmaf(w_s, v, b_s);
                    s += ex2f((xv - m) * L2E);
                }
            }
            s += __shfl_xor_sync(0xFFFFFFFFu, s, 1);
            s += __shfl_xor_sync(0xFFFFFFFFu, s, 2);
            sself += __shfl_xor_sync(0xFFFFFFFFu, sself, 1);
            sself += __shfl_xor_sync(0xFFFFFFFFu, sself, 2);
            if ((L & 3) == 0) {
                ms[row * 2 + warpN] = make_float2(m, s);
                if (cloc >= 0) SELF[row] = sself;
            }
        }
    }
    __syncthreads();

    // combine halves per row, then block-reduce
    float contrib = 0.f;
    if (tid < 128) {
        float2 h0 = ms[tid * 2], h1 = ms[tid * 2 + 1];
        float mm_ = fmaxf(h0.x, h1.x);
        float ss = h0.y * ex2f((h0.x - mm_) * L2E) + h1.y * ex2f((h1.x - mm_) * L2E);
        contrib = mm_ + lg2f(ss) * LN2 - SELF[tid];
    }
    contrib += __shfl_xor_sync(0xFFFFFFFFu, contrib, 16);
    contrib += __shfl_xor_sync(0xFFFFFFFFu, contrib, 8);
    contrib += __shfl_xor_sync(0xFFFFFFFFu, contrib, 4);
    contrib += __shfl_xor_sync(0xFFFFFFFFu, contrib, 2);
    contrib += __shfl_xor_sync(0xFFFFFFFFu, contrib, 1);
    if (L == 0) red[wid] = contrib;
    __syncthreads();
    if (tid == 0) {
        float t = 0.f;
#pragma unroll
        for (int w = 0; w < 8; w++) t += red[w];
        atomicAdd(out, t);
    }
}

// ============================ launch ============================
extern "C" void kernel_launch(void* const* d_in, const int* in_sizes, int n_in,
                              void* d_out, int out_size) {
    const float* E  = (const float*)d_in[0];
    const float* wp = (const float*)d_in[1];
    const float* bp = (const float*)d_in[2];
    float* out = (float*)d_out;

    centroid_kernel<<<(BB * NN * DD) / 256, 256>>>(E);
    zero_kernel<<<1, 1>>>(out);

    cudaFuncSetAttribute(loss_kernel, cudaFuncAttributeMaxDynamicSharedMemorySize, SMEM_TOTAL);
    loss_kernel<<<BB * (NN / 8), 256, SMEM_TOTAL>>>(E, wp, bp, out);
}